// round 1
// baseline (speedup 1.0000x reference)
#include <cuda_runtime.h>
#include <cstdint>

#define BB 8
#define NN 256
#define HH 128
#define TILE_M 64
#define THREADS 256
#define NWARPS 8
#define SE_STRIDE 132   // 128 + 4 pad, conflict-free frag loads; row = 528B (16B aligned)

// Scratch for Vx[b,n,o] (1 MB). Device-global per harness rules (no cudaMalloc).
__device__ float g_R[BB * NN * HH];

// ---------------------------------------------------------------------------
// Kernel 1: R[b,n,o] = sum_h x[b,n,h] * V_w[o,h] + V_b[o]   (fp32 exact)
// grid = 2048 (one CTA per (b,n) row), 128 threads (one per o)
// ---------------------------------------------------------------------------
__global__ void vx_kernel(const float* __restrict__ x,
                          const float* __restrict__ Vw,
                          const float* __restrict__ Vb) {
    __shared__ float xs[HH];
    int row = blockIdx.x;          // b*256 + n
    int o   = threadIdx.x;
    xs[o] = x[row * HH + o];
    __syncthreads();
    float acc = Vb[o];
    const float4* wr = reinterpret_cast<const float4*>(Vw + o * HH);
#pragma unroll
    for (int h4 = 0; h4 < HH / 4; h4++) {
        float4 w = wr[h4];
        acc += w.x * xs[h4 * 4 + 0];
        acc += w.y * xs[h4 * 4 + 1];
        acc += w.z * xs[h4 * 4 + 2];
        acc += w.w * xs[h4 * 4 + 3];
    }
    g_R[row * HH + o] = acc;
}

// ---------------------------------------------------------------------------
// Kernel 2: main GEMM + bias epilogue via mma.sync m16n8k8 tf32
//   C[m,o] = sum_h e[m,h] * U_w[o,h]
//   out[m,o] = C + (R[b,i,o] + U_b[o]) + R[b,j,o]
// Persistent grid-stride over 8192 tiles of 64 rows each.
// Warp w owns outputs o in [16w, 16w+16); its U_w fragments live in registers.
// ---------------------------------------------------------------------------
__device__ __forceinline__ uint32_t f2tf32(float f) {
    uint32_t r;
    asm("cvt.rna.tf32.f32 %0, %1;" : "=r"(r) : "f"(f));
    return r;
}

__global__ __launch_bounds__(THREADS) void edge_kernel(
    const float* __restrict__ e,
    const float* __restrict__ Uw,
    const float* __restrict__ Ub,
    float* __restrict__ out)
{
    __shared__ uint32_t sE[TILE_M * SE_STRIDE];  // e tile as rounded tf32 bits
    __shared__ float    sS[HH];                  // R[b,i,:] + U_b

    const int tid  = threadIdx.x;
    const int lane = tid & 31;
    const int warp = tid >> 5;
    const int g    = lane >> 2;    // groupID
    const int tg   = lane & 3;     // threadID_in_group
    const int o_base = warp * 16;

    // --- Load register-resident B fragments (U_w), rounded to tf32 ---
    // b0:(k=tg,   n=g) ; b1:(k=tg+4, n=g)  within (o_chunk, k_step)
    uint32_t Bf[2][16][2];
#pragma unroll
    for (int oc = 0; oc < 2; oc++) {
#pragma unroll
        for (int ks = 0; ks < 16; ks++) {
            int n  = o_base + oc * 8 + g;
            int k0 = ks * 8 + tg;
            Bf[oc][ks][0] = f2tf32(Uw[n * HH + k0]);
            Bf[oc][ks][1] = f2tf32(Uw[n * HH + k0 + 4]);
        }
    }

    const int ntiles = (BB * NN * NN) / TILE_M;  // 8192
    for (int t = blockIdx.x; t < ntiles; t += gridDim.x) {
        const int base_m = t * TILE_M;
        const int b  = base_m >> 16;
        const int i  = (base_m >> 8) & 255;
        const int j0 = base_m & 255;

        __syncthreads();  // protect sE reuse from previous iteration

        // --- Stage e tile: 64 rows x 128 fp32, rounded to tf32, float4 I/O ---
        {
            const float4* ep = reinterpret_cast<const float4*>(e + (size_t)base_m * HH);
#pragma unroll
            for (int q = 0; q < 8; q++) {
                int idx = tid + q * THREADS;   // 0..2047 float4s
                int row = idx >> 5;            // 32 float4 per row
                int c4  = idx & 31;
                float4 v = ep[idx];
                uint4 u = make_uint4(f2tf32(v.x), f2tf32(v.y), f2tf32(v.z), f2tf32(v.w));
                *reinterpret_cast<uint4*>(&sE[row * SE_STRIDE + c4 * 4]) = u;
            }
            if (tid < HH)
                sS[tid] = g_R[(b * NN + i) * HH + tid] + Ub[tid];
        }
        __syncthreads();

        // --- Compute + epilogue per 16-row m-tile ---
#pragma unroll
        for (int mt = 0; mt < TILE_M / 16; mt++) {
            float c[2][4] = {{0.f, 0.f, 0.f, 0.f}, {0.f, 0.f, 0.f, 0.f}};
#pragma unroll
            for (int ks = 0; ks < 16; ks++) {
                const uint32_t* abase = &sE[(mt * 16 + g) * SE_STRIDE + ks * 8 + tg];
                uint32_t a0 = abase[0];                   // (g,   tg)
                uint32_t a1 = abase[8 * SE_STRIDE];       // (g+8, tg)
                uint32_t a2 = abase[4];                   // (g,   tg+4)
                uint32_t a3 = abase[8 * SE_STRIDE + 4];   // (g+8, tg+4)
#pragma unroll
                for (int oc = 0; oc < 2; oc++) {
                    asm volatile(
                        "mma.sync.aligned.m16n8k8.row.col.f32.tf32.tf32.f32 "
                        "{%0,%1,%2,%3}, {%4,%5,%6,%7}, {%8,%9}, {%0,%1,%2,%3};"
                        : "+f"(c[oc][0]), "+f"(c[oc][1]), "+f"(c[oc][2]), "+f"(c[oc][3])
                        : "r"(a0), "r"(a1), "r"(a2), "r"(a3),
                          "r"(Bf[oc][ks][0]), "r"(Bf[oc][ks][1]));
                }
            }
            // Epilogue: C rows (g, g+8); cols (2tg, 2tg+1) within each 8-chunk.
            const int r0 = mt * 16 + g;
            const int r1 = r0 + 8;
            const int jr0 = j0 + r0;
            const int jr1 = j0 + r1;
            const size_t m0 = (size_t)(base_m + r0) * HH;
            const size_t m1 = (size_t)(base_m + r1) * HH;
#pragma unroll
            for (int oc = 0; oc < 2; oc++) {
                int o = o_base + oc * 8 + 2 * tg;
                float2 s  = *reinterpret_cast<const float2*>(&sS[o]);
                float2 R0 = *reinterpret_cast<const float2*>(&g_R[(b * NN + jr0) * HH + o]);
                float2 R1 = *reinterpret_cast<const float2*>(&g_R[(b * NN + jr1) * HH + o]);
                float2 v0 = make_float2(c[oc][0] + s.x + R0.x, c[oc][1] + s.y + R0.y);
                float2 v1 = make_float2(c[oc][2] + s.x + R1.x, c[oc][3] + s.y + R1.y);
                *reinterpret_cast<float2*>(&out[m0 + o]) = v0;
                *reinterpret_cast<float2*>(&out[m1 + o]) = v1;
            }
        }
    }
}

// ---------------------------------------------------------------------------
// Inputs (metadata order): x, e, U_w, U_b, V_w, V_b. Output: fp32 [8,256,256,128].
// ---------------------------------------------------------------------------
extern "C" void kernel_launch(void* const* d_in, const int* in_sizes, int n_in,
                              void* d_out, int out_size) {
    const float* x  = (const float*)d_in[0];
    const float* e  = (const float*)d_in[1];
    const float* Uw = (const float*)d_in[2];
    const float* Ub = (const float*)d_in[3];
    const float* Vw = (const float*)d_in[4];
    const float* Vb = (const float*)d_in[5];
    float* out = (float*)d_out;

    vx_kernel<<<BB * NN, HH>>>(x, Vw, Vb);
    edge_kernel<<<592, THREADS>>>(e, Uw, Ub, out);
}

// round 3
// speedup vs baseline: 1.1224x; 1.1224x over previous
#include <cuda_runtime.h>
#include <cstdint>
#include <cstddef>

#define THREADS 256
#define TILE_ROWS 64
#define STRIDE 132                          // floats; 528B rows, conflict-free frags
#define TILE_SMEM_FLOATS (TILE_ROWS * STRIDE)
#define TILE_SMEM_BYTES (TILE_SMEM_FLOATS * 4)   // 33792
#define NTILES 8192                         // 8*256*256 / 64
#define EGRID 152

__device__ float g_R[8 * 256 * 128];        // Vx scratch (1 MB)

__device__ __forceinline__ uint32_t f2tf32(float f) {
    uint32_t r;
    asm("cvt.rna.tf32.f32 %0, %1;" : "=r"(r) : "f"(f));
    return r;
}
__device__ __forceinline__ uint32_t smem_u32(const void* p) {
    uint32_t a;
    asm("{ .reg .u64 t; cvta.to.shared.u64 t, %1; cvt.u32.u64 %0, t; }" : "=r"(a) : "l"(p));
    return a;
}

// Stage one 64x128 fp32 tile (raw) into SMEM via cp.async.cg (L1-bypass), 1 group.
__device__ __forceinline__ void stage_cp(uint32_t sdst, const float* __restrict__ src, int tid) {
#pragma unroll
    for (int q = 0; q < 8; q++) {
        int idx = tid + q * THREADS;                       // 0..2047 x 16B
        uint32_t dst = sdst + (uint32_t)((idx >> 5) * (STRIDE * 4) + (idx & 31) * 16);
        asm volatile("cp.async.cg.shared.global [%0], [%1], 16;"
                     :: "r"(dst), "l"(src + (size_t)idx * 4) : "memory");
    }
    asm volatile("cp.async.commit_group;" ::: "memory");
}

// ---------------------------------------------------------------------------
// Kernel 1: R[b,n,o] = x[b,n,:] . V_w[o,:] + V_b[o]   (fp32 exact)
// grid 128, block 256; CTA handles 16 rows, x rows staged in SMEM.
// ---------------------------------------------------------------------------
__global__ __launch_bounds__(THREADS) void vx_kernel(const float* __restrict__ x,
                                                     const float* __restrict__ Vw,
                                                     const float* __restrict__ Vb) {
    __shared__ float xs[16 * 128];
    int tid = threadIdx.x;
    int rbase = blockIdx.x * 16;
    const float4* xp = reinterpret_cast<const float4*>(x + rbase * 128);
    float4* xsp = reinterpret_cast<float4*>(xs);
#pragma unroll
    for (int q = 0; q < 2; q++) xsp[tid + q * THREADS] = xp[tid + q * THREADS];
    __syncthreads();

    int o  = tid & 127;
    int r0 = tid >> 7;     // 0 or 1, shared by whole warp -> LDS broadcast
    float acc[8];
    float vb = Vb[o];
#pragma unroll
    for (int k = 0; k < 8; k++) acc[k] = vb;
    const float4* wr = reinterpret_cast<const float4*>(Vw + o * 128);
#pragma unroll
    for (int h4 = 0; h4 < 32; h4++) {
        float4 w = wr[h4];
#pragma unroll
        for (int k = 0; k < 8; k++) {
            const float* xr = xs + (r0 + 2 * k) * 128 + h4 * 4;
            acc[k] += w.x * xr[0] + w.y * xr[1] + w.z * xr[2] + w.w * xr[3];
        }
    }
#pragma unroll
    for (int k = 0; k < 8; k++)
        g_R[(rbase + r0 + 2 * k) * 128 + o] = acc[k];
}

// ---------------------------------------------------------------------------
// Kernel 2: tf32 mma.sync GEMM, n=32 outputs per warp (A duplication 4x).
//   out[m,o] = e[m,:].Uw[o,:] + (R[b,i,o]+Ub[o]) + R[b,j,o]
// 8 warps = 2 row-groups (32 rows) x 4 n-chunks (32 outputs).
// Persistent grid, cp.async double-buffered tiles.
// ---------------------------------------------------------------------------
__global__ __launch_bounds__(THREADS, 1) void edge_kernel(
    const float* __restrict__ e, const float* __restrict__ Uw,
    const float* __restrict__ Ub, float* __restrict__ out)
{
    extern __shared__ float smem[];
    const int tid  = threadIdx.x;
    const int lane = tid & 31;
    const int warp = tid >> 5;
    const int g    = lane >> 2;
    const int tg   = lane & 3;
    const int rg   = warp >> 2;          // row group: 0/1
    const int obase = (warp & 3) * 32;   // n chunk
    uint32_t sbase = smem_u32(smem);

    // --- Register-resident B fragments: 4 oc x 16 ks x 2 = 128 regs ---
    uint32_t Bf[4][16][2];
#pragma unroll
    for (int oc = 0; oc < 4; oc++)
#pragma unroll
        for (int ks = 0; ks < 16; ks++) {
            int n  = obase + oc * 8 + g;
            int k0 = ks * 8 + tg;
            Bf[oc][ks][0] = f2tf32(Uw[n * 128 + k0]);
            Bf[oc][ks][1] = f2tf32(Uw[n * 128 + k0 + 4]);
        }
    // --- U_b in registers (float2 per oc) ---
    float2 ub2[4];
#pragma unroll
    for (int oc = 0; oc < 4; oc++)
        ub2[oc] = *reinterpret_cast<const float2*>(Ub + obase + oc * 8 + 2 * tg);

    const int G  = (int)gridDim.x;
    const int t0 = (int)blockIdx.x;
    if (t0 < NTILES) stage_cp(sbase, e + (size_t)t0 * (TILE_ROWS * 128), tid);

    int s = 0;
    for (int t = t0; t < NTILES; t += G, s++) {
        const int p = s & 1;
        asm volatile("cp.async.wait_group 0;" ::: "memory");
        __syncthreads();                     // tile p ready; all warps done with p^1
        const int tn = t + G;
        if (tn < NTILES)
            stage_cp(sbase + (uint32_t)((p ^ 1) * TILE_SMEM_BYTES),
                     e + (size_t)tn * (TILE_ROWS * 128), tid);   // overlaps compute

        const int base_m = t * TILE_ROWS;
        const int b  = base_m >> 16;
        const int i  = (base_m >> 8) & 255;
        const int j0 = base_m & 255;

        // row-bias: R[b,i,o] + Ub[o]
        float2 si2[4];
        const float* Ri = g_R + (size_t)(b * 256 + i) * 128;
#pragma unroll
        for (int oc = 0; oc < 4; oc++) {
            float2 r = *reinterpret_cast<const float2*>(Ri + obase + oc * 8 + 2 * tg);
            si2[oc] = make_float2(r.x + ub2[oc].x, r.y + ub2[oc].y);
        }

        const float* sA = smem + p * TILE_SMEM_FLOATS;
#pragma unroll
        for (int mt = 0; mt < 2; mt++) {
            const int rowb = rg * 32 + mt * 16;
            float c[4][4];
#pragma unroll
            for (int oc = 0; oc < 4; oc++)
#pragma unroll
                for (int q = 0; q < 4; q++) c[oc][q] = 0.f;

#pragma unroll
            for (int ks = 0; ks < 16; ks++) {
                const float* ap = sA + (rowb + g) * STRIDE + ks * 8 + tg;
                uint32_t a0 = f2tf32(ap[0]);
                uint32_t a1 = f2tf32(ap[8 * STRIDE]);
                uint32_t a2 = f2tf32(ap[4]);
                uint32_t a3 = f2tf32(ap[8 * STRIDE + 4]);
#pragma unroll
                for (int oc = 0; oc < 4; oc++) {
                    asm volatile(
                        "mma.sync.aligned.m16n8k8.row.col.f32.tf32.tf32.f32 "
                        "{%0,%1,%2,%3}, {%4,%5,%6,%7}, {%8,%9}, {%0,%1,%2,%3};"
                        : "+f"(c[oc][0]), "+f"(c[oc][1]), "+f"(c[oc][2]), "+f"(c[oc][3])
                        : "r"(a0), "r"(a1), "r"(a2), "r"(a3),
                          "r"(Bf[oc][ks][0]), "r"(Bf[oc][ks][1]));
                }
            }

            // Epilogue: rows r0, r0+8; cols 2tg,2tg+1 within each 8-chunk
            const int r0 = rowb + g;
            const int r1 = r0 + 8;
            const size_t m0 = (size_t)(base_m + r0) * 128;
            const size_t m1 = (size_t)(base_m + r1) * 128;
            const float* Rj0 = g_R + (size_t)(b * 256 + j0 + r0) * 128;
            const float* Rj1 = g_R + (size_t)(b * 256 + j0 + r1) * 128;
#pragma unroll
            for (int oc = 0; oc < 4; oc++) {
                int o = obase + oc * 8 + 2 * tg;
                float2 R0 = *reinterpret_cast<const float2*>(Rj0 + o);
                float2 R1 = *reinterpret_cast<const float2*>(Rj1 + o);
                float2 v0 = make_float2(c[oc][0] + si2[oc].x + R0.x,
                                        c[oc][1] + si2[oc].y + R0.y);
                float2 v1 = make_float2(c[oc][2] + si2[oc].x + R1.x,
                                        c[oc][3] + si2[oc].y + R1.y);
                *reinterpret_cast<float2*>(out + m0 + o) = v0;
                *reinterpret_cast<float2*>(out + m1 + o) = v1;
            }
        }
    }
}

// ---------------------------------------------------------------------------
// Inputs (metadata order): x, e, U_w, U_b, V_w, V_b. Output fp32 [8,256,256,128].
// ---------------------------------------------------------------------------
extern "C" void kernel_launch(void* const* d_in, const int* in_sizes, int n_in,
                              void* d_out, int out_size) {
    const float* x  = (const float*)d_in[0];
    const float* e  = (const float*)d_in[1];
    const float* Uw = (const float*)d_in[2];
    const float* Ub = (const float*)d_in[3];
    const float* Vw = (const float*)d_in[4];
    const float* Vb = (const float*)d_in[5];
    float* out = (float*)d_out;

    cudaFuncSetAttribute(edge_kernel, cudaFuncAttributeMaxDynamicSharedMemorySize,
                         2 * TILE_SMEM_BYTES);

    vx_kernel<<<128, THREADS>>>(x, Vw, Vb);
    edge_kernel<<<EGRID, THREADS, 2 * TILE_SMEM_BYTES>>>(e, Uw, Ub, out);
}

// round 4
// speedup vs baseline: 1.2153x; 1.0828x over previous
#include <cuda_runtime.h>
#include <cstdint>
#include <cstddef>

#define THREADS 128
#define TILE_ROWS 32
#define STRIDE 132                               // floats; 528B rows
#define TILE_SMEM_FLOATS (TILE_ROWS * STRIDE)
#define TILE_SMEM_BYTES (TILE_SMEM_FLOATS * 4)   // 16896
#define NTILES 16384                             // 8*256*256 / 32
#define EGRID 444                                // 3 * 148

__device__ float g_R2[8 * 256 * 128];   // Vx + 0.5*Ub  (1 MB)
__device__ float g_P[16 * 16 * 32 * 2]; // packed tf32(rna) U_w fragments (64 KB)

__device__ __forceinline__ uint32_t f2tf32(float f) {
    uint32_t r;
    asm("cvt.rna.tf32.f32 %0, %1;" : "=r"(r) : "f"(f));
    return r;
}
__device__ __forceinline__ uint32_t smem_u32(const void* p) {
    uint32_t a;
    asm("{ .reg .u64 t; cvta.to.shared.u64 t, %1; cvt.u32.u64 %0, t; }" : "=r"(a) : "l"(p));
    return a;
}

// Stage one 32x128 fp32 tile into SMEM via cp.async.cg (L1 bypass).
__device__ __forceinline__ void stage_cp(uint32_t sdst, const float* __restrict__ src, int tid) {
#pragma unroll
    for (int q = 0; q < 8; q++) {
        int idx = tid + q * THREADS;                       // 0..1023 x 16B
        uint32_t dst = sdst + (uint32_t)((idx >> 5) * (STRIDE * 4) + (idx & 31) * 16);
        asm volatile("cp.async.cg.shared.global [%0], [%1], 16;"
                     :: "r"(dst), "l"(src + (size_t)idx * 4) : "memory");
    }
    asm volatile("cp.async.commit_group;" ::: "memory");
}

// ---------------------------------------------------------------------------
// Pack kernel: g_P[nb][ks][lane] = { rna(Uw[n][k0]), rna(Uw[n][k0+4]) }
//   n = nb*8 + (lane>>2), k0 = ks*8 + (lane&3)
// ---------------------------------------------------------------------------
__global__ void pack_kernel(const float* __restrict__ Uw) {
    int p    = blockIdx.x * 256 + threadIdx.x;   // 0..8191
    int lane = p & 31;
    int ks   = (p >> 5) & 15;
    int nb   = p >> 9;
    int n    = nb * 8 + (lane >> 2);
    int k0   = ks * 8 + (lane & 3);
    uint32_t v0 = f2tf32(Uw[n * 128 + k0]);
    uint32_t v1 = f2tf32(Uw[n * 128 + k0 + 4]);
    g_P[p * 2 + 0] = __uint_as_float(v0);
    g_P[p * 2 + 1] = __uint_as_float(v1);
}

// ---------------------------------------------------------------------------
// Vx kernel: g_R2[b,n,o] = x[b,n,:] . V_w[o,:] + V_b[o] + 0.5*U_b[o]
// ---------------------------------------------------------------------------
__global__ __launch_bounds__(256) void vx_kernel(const float* __restrict__ x,
                                                 const float* __restrict__ Vw,
                                                 const float* __restrict__ Vb,
                                                 const float* __restrict__ Ub) {
    __shared__ float xs[16 * 128];
    int tid = threadIdx.x;
    int rbase = blockIdx.x * 16;
    const float4* xp = reinterpret_cast<const float4*>(x + rbase * 128);
    float4* xsp = reinterpret_cast<float4*>(xs);
#pragma unroll
    for (int q = 0; q < 2; q++) xsp[tid + q * 256] = xp[tid + q * 256];
    __syncthreads();

    int o  = tid & 127;
    int r0 = tid >> 7;     // 0/1, uniform per warp -> LDS broadcast
    float acc[8];
    float bias = Vb[o] + 0.5f * Ub[o];
#pragma unroll
    for (int k = 0; k < 8; k++) acc[k] = bias;
    const float4* wr = reinterpret_cast<const float4*>(Vw + o * 128);
#pragma unroll
    for (int h4 = 0; h4 < 32; h4++) {
        float4 w = wr[h4];
#pragma unroll
        for (int k = 0; k < 8; k++) {
            const float* xr = xs + (r0 + 2 * k) * 128 + h4 * 4;
            acc[k] += w.x * xr[0] + w.y * xr[1] + w.z * xr[2] + w.w * xr[3];
        }
    }
#pragma unroll
    for (int k = 0; k < 8; k++)
        g_R2[(rbase + r0 + 2 * k) * 128 + o] = acc[k];
}

// ---------------------------------------------------------------------------
// Edge kernel: tf32 mma.sync, 128-thr CTA, 4 warps = 4 n-chunks of 32-row tile.
//   out[m,o] = e[m,:].Uw[o,:] + R2[b,i,o] + R2[b,j,o]
// oc0,1 B resident in regs; oc2,3 streamed from packed g_P (L1-resident).
// ---------------------------------------------------------------------------
__global__ __launch_bounds__(THREADS, 3) void edge_kernel(
    const float* __restrict__ e, float* __restrict__ out)
{
    extern __shared__ float smem[];
    const int tid  = threadIdx.x;
    const int lane = tid & 31;
    const int warp = tid >> 5;
    const int g    = lane >> 2;
    const int tg   = lane & 3;
    const int obase = warp * 32;
    const int nbb   = warp * 4;
    uint32_t sbase = smem_u32(smem);

    // Resident B fragments for oc 0,1 (coalesced LDG.64 from packed store)
    uint32_t Bf[2][16][2];
#pragma unroll
    for (int oc = 0; oc < 2; oc++)
#pragma unroll
        for (int ks = 0; ks < 16; ks++) {
            float2 v = *reinterpret_cast<const float2*>(
                g_P + (size_t)(((nbb + oc) * 16 + ks) * 32 + lane) * 2);
            Bf[oc][ks][0] = __float_as_uint(v.x);
            Bf[oc][ks][1] = __float_as_uint(v.y);
        }
    const float2* P2 = reinterpret_cast<const float2*>(g_P + (size_t)(nbb + 2) * 16 * 64)
                       + lane;   // stream base for oc2 (oc3 = +16*32)

    const int G  = (int)gridDim.x;
    const int t0 = (int)blockIdx.x;
    if (t0 < NTILES) stage_cp(sbase, e + (size_t)t0 * (TILE_ROWS * 128), tid);

    int s = 0;
    for (int t = t0; t < NTILES; t += G, s++) {
        const int p = s & 1;
        asm volatile("cp.async.wait_group 0;" ::: "memory");
        __syncthreads();
        const int tn = t + G;
        if (tn < NTILES)
            stage_cp(sbase + (uint32_t)((p ^ 1) * TILE_SMEM_BYTES),
                     e + (size_t)tn * (TILE_ROWS * 128), tid);

        const int base_m = t * TILE_ROWS;
        const int b  = base_m >> 16;
        const int i  = (base_m >> 8) & 255;
        const int j0 = base_m & 255;

        const uint32_t* sA = reinterpret_cast<const uint32_t*>(smem + p * TILE_SMEM_FLOATS);
        float c[2][4][4];
#pragma unroll
        for (int mt = 0; mt < 2; mt++)
#pragma unroll
            for (int oc = 0; oc < 4; oc++)
#pragma unroll
                for (int q = 0; q < 4; q++) c[mt][oc][q] = 0.f;

#pragma unroll
        for (int ks = 0; ks < 16; ks++) {
            float2 bs2 = P2[ks * 32];             // oc2, LDG.64 L1-hit
            float2 bs3 = P2[(16 + ks) * 32];      // oc3
            uint32_t B2[2] = { __float_as_uint(bs2.x), __float_as_uint(bs2.y) };
            uint32_t B3[2] = { __float_as_uint(bs3.x), __float_as_uint(bs3.y) };
#pragma unroll
            for (int mt = 0; mt < 2; mt++) {
                const uint32_t* ap = sA + (mt * 16 + g) * STRIDE + ks * 8 + tg;
                uint32_t a0 = ap[0];              // raw fp32 bits; HMMA truncates
                uint32_t a1 = ap[8 * STRIDE];
                uint32_t a2 = ap[4];
                uint32_t a3 = ap[8 * STRIDE + 4];
#pragma unroll
                for (int oc = 0; oc < 2; oc++)
                    asm volatile(
                        "mma.sync.aligned.m16n8k8.row.col.f32.tf32.tf32.f32 "
                        "{%0,%1,%2,%3}, {%4,%5,%6,%7}, {%8,%9}, {%0,%1,%2,%3};"
                        : "+f"(c[mt][oc][0]), "+f"(c[mt][oc][1]),
                          "+f"(c[mt][oc][2]), "+f"(c[mt][oc][3])
                        : "r"(a0), "r"(a1), "r"(a2), "r"(a3),
                          "r"(Bf[oc][ks][0]), "r"(Bf[oc][ks][1]));
                asm volatile(
                    "mma.sync.aligned.m16n8k8.row.col.f32.tf32.tf32.f32 "
                    "{%0,%1,%2,%3}, {%4,%5,%6,%7}, {%8,%9}, {%0,%1,%2,%3};"
                    : "+f"(c[mt][2][0]), "+f"(c[mt][2][1]),
                      "+f"(c[mt][2][2]), "+f"(c[mt][2][3])
                    : "r"(a0), "r"(a1), "r"(a2), "r"(a3), "r"(B2[0]), "r"(B2[1]));
                asm volatile(
                    "mma.sync.aligned.m16n8k8.row.col.f32.tf32.tf32.f32 "
                    "{%0,%1,%2,%3}, {%4,%5,%6,%7}, {%8,%9}, {%0,%1,%2,%3};"
                    : "+f"(c[mt][3][0]), "+f"(c[mt][3][1]),
                      "+f"(c[mt][3][2]), "+f"(c[mt][3][3])
                    : "r"(a0), "r"(a1), "r"(a2), "r"(a3), "r"(B3[0]), "r"(B3[1]));
            }
        }

        // Epilogue: out = C + R2[b,i] + R2[b,j(row)]
        const float* Ri = g_R2 + (size_t)(b * 256 + i) * 128;
#pragma unroll
        for (int mt = 0; mt < 2; mt++) {
            const int r0 = mt * 16 + g;
            const int r1 = r0 + 8;
            const size_t m0 = (size_t)(base_m + r0) * 128;
            const size_t m1 = (size_t)(base_m + r1) * 128;
            const float* Rj0 = g_R2 + (size_t)(b * 256 + j0 + r0) * 128;
            const float* Rj1 = g_R2 + (size_t)(b * 256 + j0 + r1) * 128;
#pragma unroll
            for (int oc = 0; oc < 4; oc++) {
                const int o = obase + oc * 8 + 2 * tg;
                float2 si = *reinterpret_cast<const float2*>(Ri + o);
                float2 R0 = *reinterpret_cast<const float2*>(Rj0 + o);
                float2 R1 = *reinterpret_cast<const float2*>(Rj1 + o);
                float2 v0 = make_float2(c[mt][oc][0] + si.x + R0.x,
                                        c[mt][oc][1] + si.y + R0.y);
                float2 v1 = make_float2(c[mt][oc][2] + si.x + R1.x,
                                        c[mt][oc][3] + si.y + R1.y);
                *reinterpret_cast<float2*>(out + m0 + o) = v0;
                *reinterpret_cast<float2*>(out + m1 + o) = v1;
            }
        }
    }
}

// ---------------------------------------------------------------------------
// Inputs (metadata order): x, e, U_w, U_b, V_w, V_b. Output fp32 [8,256,256,128].
// ---------------------------------------------------------------------------
extern "C" void kernel_launch(void* const* d_in, const int* in_sizes, int n_in,
                              void* d_out, int out_size) {
    const float* x  = (const float*)d_in[0];
    const float* e  = (const float*)d_in[1];
    const float* Uw = (const float*)d_in[2];
    const float* Ub = (const float*)d_in[3];
    const float* Vw = (const float*)d_in[4];
    const float* Vb = (const float*)d_in[5];
    float* out = (float*)d_out;

    cudaFuncSetAttribute(edge_kernel, cudaFuncAttributeMaxDynamicSharedMemorySize,
                         2 * TILE_SMEM_BYTES);

    pack_kernel<<<32, 256>>>(Uw);
    vx_kernel<<<128, 256>>>(x, Vw, Vb, Ub);
    edge_kernel<<<EGRID, THREADS, 2 * TILE_SMEM_BYTES>>>(e, out);
}

// round 5
// speedup vs baseline: 1.3206x; 1.0867x over previous
#include <cuda_runtime.h>
#include <cstdint>
#include <cstddef>

#define THREADS 128
#define TILE_ROWS 32
#define STRIDE 132                               // floats; 528B rows
#define TILE_SMEM_FLOATS (TILE_ROWS * STRIDE)
#define TILE_SMEM_BYTES (TILE_SMEM_FLOATS * 4)   // 16896
#define NSTAGE 3
#define NTILES 16384                             // 8*256*256 / 32
#define EGRID 444                                // 3 * 148

__device__ float g_R2[8 * 256 * 128];     // Vx + 0.5*Ub  (1 MB)
__device__ float g_P2[8 * 16 * 32 * 2];   // resident B fragments (oc 0,1 per warp), 32 KB
__device__ float4 g_Q[4 * 16 * 32];       // streamed B fragment pairs (oc 2,3), 32 KB

__device__ __forceinline__ uint32_t f2tf32(float f) {
    uint32_t r;
    asm("cvt.rna.tf32.f32 %0, %1;" : "=r"(r) : "f"(f));
    return r;
}
__device__ __forceinline__ uint32_t smem_u32(const void* p) {
    uint32_t a;
    asm("{ .reg .u64 t; cvta.to.shared.u64 t, %1; cvt.u32.u64 %0, t; }" : "=r"(a) : "l"(p));
    return a;
}

// Stage one 32x128 fp32 tile into SMEM via cp.async.cg; ALWAYS commits a group.
__device__ __forceinline__ void stage_cp(uint32_t sdst, const float* __restrict__ src,
                                         int tid, bool pred) {
    if (pred) {
#pragma unroll
        for (int q = 0; q < 8; q++) {
            int idx = tid + q * THREADS;                   // 0..1023 x 16B
            uint32_t dst = sdst + (uint32_t)((idx >> 5) * (STRIDE * 4) + (idx & 31) * 16);
            asm volatile("cp.async.cg.shared.global [%0], [%1], 16;"
                         :: "r"(dst), "l"(src + (size_t)idx * 4) : "memory");
        }
    }
    asm volatile("cp.async.commit_group;" ::: "memory");
}

// ---------------------------------------------------------------------------
// Pack kernel. Column-permuted mapping: mma col c of chunk oc in warp w holds
// Uw row o = w*32 + 8*(c>>1) + 2*oc + (c&1)  ->  thread (g,tg) owns o-range
// [w*32 + 8*tg, +8) contiguously in the epilogue.
//   p <  4096 : g_P2 (oc 0,1 resident fragments)
//   p >= 4096 : g_Q  (oc 2,3 streamed fragment pairs, float4)
// ---------------------------------------------------------------------------
__global__ void pack_kernel(const float* __restrict__ Uw) {
    int p = blockIdx.x * 256 + threadIdx.x;      // 0..6143
    if (p < 4096) {
        int lane = p & 31, ks = (p >> 5) & 15, q = p >> 9;   // q = warp*2 + oc
        int w = q >> 1, oc = q & 1, g = lane >> 2;
        int row = w * 32 + 8 * (g >> 1) + 2 * oc + (g & 1);
        int k0  = ks * 8 + (lane & 3);
        g_P2[p * 2 + 0] = __uint_as_float(f2tf32(Uw[row * 128 + k0]));
        g_P2[p * 2 + 1] = __uint_as_float(f2tf32(Uw[row * 128 + k0 + 4]));
    } else {
        int r = p - 4096;
        int lane = r & 31, ks = (r >> 5) & 15, w = r >> 9;
        int g = lane >> 2;
        int row2 = w * 32 + 8 * (g >> 1) + 4 + (g & 1);      // oc=2
        int row3 = row2 + 2;                                  // oc=3
        int k0   = ks * 8 + (lane & 3);
        g_Q[(w * 16 + ks) * 32 + lane] = make_float4(
            __uint_as_float(f2tf32(Uw[row2 * 128 + k0])),
            __uint_as_float(f2tf32(Uw[row2 * 128 + k0 + 4])),
            __uint_as_float(f2tf32(Uw[row3 * 128 + k0])),
            __uint_as_float(f2tf32(Uw[row3 * 128 + k0 + 4])));
    }
}

// ---------------------------------------------------------------------------
// Vx kernel: g_R2[b,n,o] = x[b,n,:] . V_w[o,:] + V_b[o] + 0.5*U_b[o]
// ---------------------------------------------------------------------------
__global__ __launch_bounds__(256) void vx_kernel(const float* __restrict__ x,
                                                 const float* __restrict__ Vw,
                                                 const float* __restrict__ Vb,
                                                 const float* __restrict__ Ub) {
    __shared__ float xs[16 * 128];
    int tid = threadIdx.x;
    int rbase = blockIdx.x * 16;
    const float4* xp = reinterpret_cast<const float4*>(x + rbase * 128);
    float4* xsp = reinterpret_cast<float4*>(xs);
#pragma unroll
    for (int q = 0; q < 2; q++) xsp[tid + q * 256] = xp[tid + q * 256];
    __syncthreads();

    int o  = tid & 127;
    int r0 = tid >> 7;
    float acc[8];
    float bias = Vb[o] + 0.5f * Ub[o];
#pragma unroll
    for (int k = 0; k < 8; k++) acc[k] = bias;
    const float4* wr = reinterpret_cast<const float4*>(Vw + o * 128);
#pragma unroll
    for (int h4 = 0; h4 < 32; h4++) {
        float4 w = wr[h4];
#pragma unroll
        for (int k = 0; k < 8; k++) {
            const float* xr = xs + (r0 + 2 * k) * 128 + h4 * 4;
            acc[k] += w.x * xr[0] + w.y * xr[1] + w.z * xr[2] + w.w * xr[3];
        }
    }
#pragma unroll
    for (int k = 0; k < 8; k++)
        g_R2[(rbase + r0 + 2 * k) * 128 + o] = acc[k];
}

// ---------------------------------------------------------------------------
// Edge kernel: tf32 mma.sync; 4 warps = 4 n-chunks of a 32-row tile.
//   out[m,o] = e[m,:].Uw[o,:] + R2[b,i,o] + R2[b,j,o]
// 3-stage cp.async pipeline; bias rows prefetched to regs before the mainloop;
// contiguous-o epilogue (LDG.128/STG.128).
// ---------------------------------------------------------------------------
__global__ __launch_bounds__(THREADS, 3) void edge_kernel(
    const float* __restrict__ e, float* __restrict__ out)
{
    extern __shared__ float smem[];
    const int tid  = threadIdx.x;
    const int lane = tid & 31;
    const int warp = tid >> 5;
    const int g    = lane >> 2;
    const int tg   = lane & 3;
    const int ob8  = warp * 32 + 8 * tg;     // thread's contiguous o-range start
    uint32_t sbase = smem_u32(smem);

    // Resident B fragments (oc 0,1): coalesced one-time loads
    uint32_t Bf[2][16][2];
#pragma unroll
    for (int oc = 0; oc < 2; oc++)
#pragma unroll
        for (int ks = 0; ks < 16; ks++) {
            float2 v = *reinterpret_cast<const float2*>(
                g_P2 + (size_t)(((warp * 2 + oc) * 16 + ks) * 32 + lane) * 2);
            Bf[oc][ks][0] = __float_as_uint(v.x);
            Bf[oc][ks][1] = __float_as_uint(v.y);
        }
    const float4* Qp = g_Q + (size_t)(warp * 16) * 32 + lane;

    const int G  = (int)gridDim.x;
    const int t0 = (int)blockIdx.x;
    stage_cp(sbase, e + (size_t)t0 * (TILE_ROWS * 128), tid, true);
    {
        const int t1 = t0 + G;
        stage_cp(sbase + TILE_SMEM_BYTES,
                 e + (size_t)t1 * (TILE_ROWS * 128), tid, t1 < NTILES);
    }

    int s = 0;
    for (int t = t0; t < NTILES; t += G, s++) {
        const int buf = s % NSTAGE;
        const int base_m = t * TILE_ROWS;
        const int b  = base_m >> 16;
        const int i  = (base_m >> 8) & 255;
        const int j0 = base_m & 255;

        // ---- Prefetch bias rows into registers (overlaps cp.async wait + mma) ----
        float4 Rp[4][2];
        {
            const float* Rbase = g_R2 + ((size_t)(b * 256 + j0) * 128 + ob8);
#pragma unroll
            for (int q = 0; q < 4; q++) {
                int row = (q >> 1) * 16 + (q & 1) * 8 + g;
                Rp[q][0] = *reinterpret_cast<const float4*>(Rbase + (size_t)row * 128);
                Rp[q][1] = *reinterpret_cast<const float4*>(Rbase + (size_t)row * 128 + 4);
            }
            const float* Ri = g_R2 + ((size_t)(b * 256 + i) * 128 + ob8);
            float4 s0 = *reinterpret_cast<const float4*>(Ri);
            float4 s1 = *reinterpret_cast<const float4*>(Ri + 4);
#pragma unroll
            for (int q = 0; q < 4; q++) {
                Rp[q][0].x += s0.x; Rp[q][0].y += s0.y; Rp[q][0].z += s0.z; Rp[q][0].w += s0.w;
                Rp[q][1].x += s1.x; Rp[q][1].y += s1.y; Rp[q][1].z += s1.z; Rp[q][1].w += s1.w;
            }
        }

        asm volatile("cp.async.wait_group 1;" ::: "memory");
        __syncthreads();
        {
            const int tn = t + 2 * G;
            stage_cp(sbase + (uint32_t)(((s + 2) % NSTAGE) * TILE_SMEM_BYTES),
                     e + (size_t)tn * (TILE_ROWS * 128), tid, tn < NTILES);
        }

        const uint32_t* sA = reinterpret_cast<const uint32_t*>(smem + buf * TILE_SMEM_FLOATS);
        float c[2][4][4];
#pragma unroll
        for (int mt = 0; mt < 2; mt++)
#pragma unroll
            for (int oc = 0; oc < 4; oc++)
#pragma unroll
                for (int q = 0; q < 4; q++) c[mt][oc][q] = 0.f;

#pragma unroll
        for (int ks = 0; ks < 16; ks++) {
            float4 bs = Qp[ks * 32];              // streamed oc2/oc3 pair, L1-hit
            uint32_t B2[2] = { __float_as_uint(bs.x), __float_as_uint(bs.y) };
            uint32_t B3[2] = { __float_as_uint(bs.z), __float_as_uint(bs.w) };
#pragma unroll
            for (int mt = 0; mt < 2; mt++) {
                const uint32_t* ap = sA + (mt * 16 + g) * STRIDE + ks * 8 + tg;
                uint32_t a0 = ap[0];              // raw fp32 bits; HMMA truncates
                uint32_t a1 = ap[8 * STRIDE];
                uint32_t a2 = ap[4];
                uint32_t a3 = ap[8 * STRIDE + 4];
#pragma unroll
                for (int oc = 0; oc < 2; oc++)
                    asm volatile(
                        "mma.sync.aligned.m16n8k8.row.col.f32.tf32.tf32.f32 "
                        "{%0,%1,%2,%3}, {%4,%5,%6,%7}, {%8,%9}, {%0,%1,%2,%3};"
                        : "+f"(c[mt][oc][0]), "+f"(c[mt][oc][1]),
                          "+f"(c[mt][oc][2]), "+f"(c[mt][oc][3])
                        : "r"(a0), "r"(a1), "r"(a2), "r"(a3),
                          "r"(Bf[oc][ks][0]), "r"(Bf[oc][ks][1]));
                asm volatile(
                    "mma.sync.aligned.m16n8k8.row.col.f32.tf32.tf32.f32 "
                    "{%0,%1,%2,%3}, {%4,%5,%6,%7}, {%8,%9}, {%0,%1,%2,%3};"
                    : "+f"(c[mt][2][0]), "+f"(c[mt][2][1]),
                      "+f"(c[mt][2][2]), "+f"(c[mt][2][3])
                    : "r"(a0), "r"(a1), "r"(a2), "r"(a3), "r"(B2[0]), "r"(B2[1]));
                asm volatile(
                    "mma.sync.aligned.m16n8k8.row.col.f32.tf32.tf32.f32 "
                    "{%0,%1,%2,%3}, {%4,%5,%6,%7}, {%8,%9}, {%0,%1,%2,%3};"
                    : "+f"(c[mt][3][0]), "+f"(c[mt][3][1]),
                      "+f"(c[mt][3][2]), "+f"(c[mt][3][3])
                    : "r"(a0), "r"(a1), "r"(a2), "r"(a3), "r"(B3[0]), "r"(B3[1]));
            }
        }

        // ---- Epilogue: contiguous 8-float slice per thread per row ----
#pragma unroll
        for (int q = 0; q < 4; q++) {
            const int mt = q >> 1;
            const int h2 = (q & 1) * 2;           // 0 for rows g..; 2 for rows g+8..
            const int row = (q >> 1) * 16 + (q & 1) * 8 + g;
            float4 v0 = make_float4(c[mt][0][h2]     + Rp[q][0].x,
                                    c[mt][0][h2 + 1] + Rp[q][0].y,
                                    c[mt][1][h2]     + Rp[q][0].z,
                                    c[mt][1][h2 + 1] + Rp[q][0].w);
            float4 v1 = make_float4(c[mt][2][h2]     + Rp[q][1].x,
                                    c[mt][2][h2 + 1] + Rp[q][1].y,
                                    c[mt][3][h2]     + Rp[q][1].z,
                                    c[mt][3][h2 + 1] + Rp[q][1].w);
            float* op = out + ((size_t)(base_m + row) * 128 + ob8);
            *reinterpret_cast<float4*>(op)     = v0;
            *reinterpret_cast<float4*>(op + 4) = v1;
        }
    }
}

// ---------------------------------------------------------------------------
// Inputs (metadata order): x, e, U_w, U_b, V_w, V_b. Output fp32 [8,256,256,128].
// ---------------------------------------------------------------------------
extern "C" void kernel_launch(void* const* d_in, const int* in_sizes, int n_in,
                              void* d_out, int out_size) {
    const float* x  = (const float*)d_in[0];
    const float* e  = (const float*)d_in[1];
    const float* Uw = (const float*)d_in[2];
    const float* Ub = (const float*)d_in[3];
    const float* Vw = (const float*)d_in[4];
    const float* Vb = (const float*)d_in[5];
    float* out = (float*)d_out;

    cudaFuncSetAttribute(edge_kernel, cudaFuncAttributeMaxDynamicSharedMemorySize,
                         NSTAGE * TILE_SMEM_BYTES);

    pack_kernel<<<24, 256>>>(Uw);
    vx_kernel<<<128, 256>>>(x, Vw, Vb, Ub);
    edge_kernel<<<EGRID, THREADS, NSTAGE * TILE_SMEM_BYTES>>>(e, out);
}